// round 13
// baseline (speedup 1.0000x reference)
#include <cuda_runtime.h>
#include <cuda_fp16.h>
#include <cstdint>

// fullConv4d via fp16 mma.sync m16n8k16 (fp32 accum). M=spatial, N=co, K=ci16.
// R13 = R12 (double-buffered cp.async, kd-register-chain, 2 CTA/SM) with:
//  - slab rows 16B pitch, ci-half regions, t padded to 32/d' -> kt=0 ldmatrix
//    fragments 128B-aligned (1 wf/matrix); kt=1,2 unchanged (2 wf).
//  - per-kh weights double-buffered in the same cp.async groups.
//  - prep_w folded into prep_x (extra block) to kill the serial launch.

#define ST_T 1
#define ST_D 24
#define ST_W 576
#define ST_H 13824
#define ST_C 331776

#define HALFB   20480                       // 1280 rows * 16B  (one ci-half region)
#define SLABB   40960                       // 2 halves per buffer
#define WSB     13824                       // 27 taps * 512B (per-kh)
#define SMEM_BYTES (2 * SLABB + 2 * WSB)    // 109568

__device__ uint4 g_xh[1327104];             // 663552 points * 32B (fp16, ci16)
__device__ uint4 g_wf[2592];                // 81 taps * 32 lanes * 16B

static __device__ __forceinline__ uint32_t smem_u32(const void* p) {
    uint32_t a;
    asm("{ .reg .u64 t; cvta.to.shared.u64 t, %1; cvt.u32.u64 %0, t; }" : "=r"(a) : "l"(p));
    return a;
}

static __device__ __forceinline__ uint32_t pack2(float a, float b) {
    __half2 h = __floats2half2_rn(a, b);
    return *reinterpret_cast<uint32_t*>(&h);
}

static __device__ __forceinline__ void cpa16(uint32_t dst, const void* src, uint32_t srcsz) {
    asm volatile("cp.async.cg.shared.global [%0], [%1], 16, %2;"
                 :: "r"(dst), "l"(src), "r"(srcsz));
}

static __device__ __forceinline__ void mma16816(float* d, uint32_t a0, uint32_t a1,
                                                uint32_t a2, uint32_t a3,
                                                uint32_t b0, uint32_t b1) {
    asm volatile(
        "mma.sync.aligned.m16n8k16.row.col.f32.f16.f16.f32 "
        "{%0,%1,%2,%3}, {%4,%5,%6,%7}, {%8,%9}, {%0,%1,%2,%3};"
        : "+f"(d[0]), "+f"(d[1]), "+f"(d[2]), "+f"(d[3])
        : "r"(a0), "r"(a1), "r"(a2), "r"(a3), "r"(b0), "r"(b1));
}

// ---- prep: blocks 0..2591 convert x; block 2592 packs weights ----
__global__ __launch_bounds__(256)
void prep_kernel(const float* __restrict__ x, const float* __restrict__ wgt) {
    if (blockIdx.x == 2592) {
        for (int i = threadIdx.x; i < 2592; i += 256) {
            const int tl = i >> 5, l5 = i & 31;
            const int gg = l5 >> 2, cc = (l5 & 3) << 1;
            const float* wp = wgt + tl;
            #define WG(co, ci) wp[((co) * 16 + (ci)) * 81]
            const uint32_t r0 = pack2(WG(gg, cc),         WG(gg, cc + 1));
            const uint32_t r1 = pack2(WG(gg, cc + 8),     WG(gg, cc + 9));
            const uint32_t r2 = pack2(WG(gg + 8, cc),     WG(gg + 8, cc + 1));
            const uint32_t r3 = pack2(WG(gg + 8, cc + 8), WG(gg + 8, cc + 9));
            #undef WG
            g_wf[i] = make_uint4(r0, r1, r2, r3);
        }
        return;
    }
    const int idx = blockIdx.x * 256 + threadIdx.x;          // 663552 points
    int r = idx;
    const int t = r % 24; r /= 24;
    const int d = r % 24; r /= 24;
    const int w = r % 24; r /= 24;
    const int h = r % 24;
    const int b = r / 24;
    const float* p = x + (size_t)b * 16 * ST_C + h * ST_H + w * ST_W + d * ST_D + t;
    uint32_t v[8];
    #pragma unroll
    for (int j = 0; j < 8; ++j)
        v[j] = pack2(p[(2 * j) * ST_C], p[(2 * j + 1) * ST_C]);
    g_xh[idx * 2]     = make_uint4(v[0], v[1], v[2], v[3]);
    g_xh[idx * 2 + 1] = make_uint4(v[4], v[5], v[6], v[7]);
}

// ---- main ----
__global__ __launch_bounds__(256, 2)
void conv4d_hmma16t_kernel(const float* __restrict__ bias,
                           float* __restrict__ out) {
    extern __shared__ char smc[];
    const uint32_t slabAddr = smem_u32(smc);                 // buf0 | buf1 | ws0 | ws1
    const uint32_t wsAddr   = slabAddr + 2 * SLABB;

    const int tid = threadIdx.x;
    const int wid = tid >> 5;
    const int l   = tid & 31;
    const int g   = l >> 2;
    const int c   = l & 3;
    const int wo  = wid >> 2;
    const int dp  = wid & 3;

    int bi = blockIdx.x;
    const int dt = bi % 3;  bi /= 3;
    const int wt = bi % 12; bi /= 12;
    const int h  = bi % 24; bi /= 24;
    const int b  = bi;
    const int d0 = dt * 8;
    const int w0 = wt * 2;

    // slab row = ci-half region + (w'*10 + d')*32 + t'   (16B rows, t padded to 32)
    // x4 lanes: 0-7 L klo, 8-15 H(+32 rows) klo, 16-23 L khi, 24-31 H khi
    const int rowmap = (l & 8) ? (32 + (l & 7)) : (l & 7);
    const uint32_t aOff = (uint32_t)((l >> 4) * HALFB)
                        + (uint32_t)(((wo * 10 + 2 * dp) * 32 + rowmap) * 16);
    // x2 lanes: 0-7 new-d klo, 8-15 new-d khi
    const uint32_t aOff2 = (uint32_t)(((l >> 3) & 1) * HALFB)
                         + (uint32_t)(((wo * 10 + 2 * dp) * 32 + (l & 7)) * 16);

    // ---- precompute staging slots ----
    uint32_t dstOff[9];
    int      srcRest[9];
    uint32_t inR = 0, gV = 0;
    #pragma unroll
    for (int k = 0; k < 9; ++k) {
        const int i = tid + k * 256;
        dstOff[k] = 0; srcRest[k] = 0;
        if (i < 2080) {
            const int o  = i & 1;
            const int pt = i >> 1;
            const int tI = pt % 26;
            const int rr = pt / 26;
            const int dI = rr % 10;
            const int wI = rr / 10;
            inR |= (1u << k);
            dstOff[k] = (uint32_t)(o * HALFB + ((wI * 10 + dI) * 32 + tI) * 16);
            const int gw = w0 + wI - 1, gd = d0 + dI - 1, gt = tI - 1;
            if ((unsigned)gw < 24u && (unsigned)gd < 24u && (unsigned)gt < 24u) {
                srcRest[k] = (gw * 576 + gd * 24 + gt) * 32 + o * 16;
                gV |= (1u << k);
            }
        }
    }

    // valid kh planes
    int khs[3], nkh = 0;
    #pragma unroll
    for (int kh = 0; kh < 3; ++kh)
        if ((unsigned)(h + kh - 1) < 24u) khs[nkh++] = kh;

    const char* xhBase = (const char*)g_xh;
    const char* wfBase = (const char*)g_wf;

    // stage one plane: weights(kh) -> ws[buf], slab(kh) -> slab[buf]
    auto stage_plane = [&](int kh, int buf) {
        const uint32_t wsA = wsAddr + (uint32_t)(buf * WSB);
        #pragma unroll
        for (int k = 0; k < 4; ++k) {
            const int ii = tid + k * 256;
            if (ii < 864)
                cpa16(wsA + (uint32_t)(ii * 16), wfBase + (kh * 864 + ii) * 16, 16u);
        }
        const uint32_t bufAddr = slabAddr + (uint32_t)(buf * SLABB);
        const char* sp = xhBase + (long long)((b * 24 + (h + kh - 1)) * 13824) * 32;
        #pragma unroll
        for (int k = 0; k < 9; ++k) {
            if (inR & (1u << k))
                cpa16(bufAddr + dstOff[k], sp + srcRest[k],
                      (gV & (1u << k)) ? 16u : 0u);
        }
    };

    stage_plane(khs[0], 0);
    asm volatile("cp.async.commit_group;" ::: "memory");
    if (nkh > 1) {
        stage_plane(khs[1], 1);
        asm volatile("cp.async.commit_group;" ::: "memory");
    }
    int issued = (nkh > 1) ? 2 : 1;

    float acc[3][2][4];
    #pragma unroll
    for (int j = 0; j < 3; ++j)
        #pragma unroll
        for (int u = 0; u < 2; ++u)
            #pragma unroll
            for (int q = 0; q < 4; ++q) acc[j][u][q] = 0.0f;

    for (int i = 0; i < nkh; ++i) {
        if (issued - i == 2) { asm volatile("cp.async.wait_group 1;" ::: "memory"); }
        else                 { asm volatile("cp.async.wait_group 0;" ::: "memory"); }
        __syncthreads();

        const uint32_t bufAddr = slabAddr + (uint32_t)((i & 1) * SLABB);
        const uint32_t aLane   = bufAddr + aOff;
        const uint32_t aLane2  = bufAddr + aOff2;
        const uint32_t wLane   = wsAddr + (uint32_t)((i & 1) * WSB + l * 16);

        #pragma unroll
        for (int kw = 0; kw < 3; ++kw) {
            #pragma unroll
            for (int kt = 0; kt < 3; ++kt) {
                const int kwb = kw * 320;                 // 10 d' * 32 rows
                // kd = 0: full x4 per j; keep H halves for chaining
                uint32_t hk0[3], hk1[3];
                {
                    uint32_t b0, b1, b2, b3;
                    asm volatile("ld.shared.v4.b32 {%0,%1,%2,%3}, [%4];"
                                 : "=r"(b0), "=r"(b1), "=r"(b2), "=r"(b3)
                                 : "r"(wLane + (uint32_t)((kw * 9 + kt) * 512)));
                    #pragma unroll
                    for (int j = 0; j < 3; ++j) {
                        const uint32_t P = (uint32_t)((kwb + kt + 8 * j) * 16);
                        uint32_t a0, a1, a2, a3;
                        asm volatile("ldmatrix.sync.aligned.m8n8.x4.shared.b16 "
                                     "{%0,%1,%2,%3}, [%4];"
                                     : "=r"(a0), "=r"(a1), "=r"(a2), "=r"(a3)
                                     : "r"(aLane + P));
                        mma16816(acc[j][0], a0, a1, a2, a3, b0, b1);
                        mma16816(acc[j][1], a0, a1, a2, a3, b2, b3);
                        hk0[j] = a1; hk1[j] = a3;
                    }
                }
                // kd = 1, 2: one new d-row per j via x2; prev H becomes L
                #pragma unroll
                for (int kd = 1; kd < 3; ++kd) {
                    uint32_t b0, b1, b2, b3;
                    asm volatile("ld.shared.v4.b32 {%0,%1,%2,%3}, [%4];"
                                 : "=r"(b0), "=r"(b1), "=r"(b2), "=r"(b3)
                                 : "r"(wLane + (uint32_t)((kw * 9 + kd * 3 + kt) * 512)));
                    #pragma unroll
                    for (int j = 0; j < 3; ++j) {
                        const uint32_t P2 = (uint32_t)((kwb + (kd + 1) * 32 + kt + 8 * j) * 16);
                        uint32_t n0, n1;
                        asm volatile("ldmatrix.sync.aligned.m8n8.x2.shared.b16 "
                                     "{%0,%1}, [%2];"
                                     : "=r"(n0), "=r"(n1)
                                     : "r"(aLane2 + P2));
                        mma16816(acc[j][0], hk0[j], n0, hk1[j], n1, b0, b1);
                        mma16816(acc[j][1], hk0[j], n0, hk1[j], n1, b2, b3);
                        hk0[j] = n0; hk1[j] = n1;
                    }
                }
            }
        }

        if (issued < nkh) {               // nkh==3: refill buf0/ws0 with khs[2]
            __syncthreads();
            stage_plane(khs[2], 0);
            asm volatile("cp.async.commit_group;" ::: "memory");
            issued = 3;
        }
    }

    // ---- epilogue ----
    float* ob = out + (size_t)b * 16 * ST_C + (size_t)h * ST_H + (size_t)(w0 + wo) * ST_W;
    const int dE = d0 + 2 * dp, dO = dE + 1;
    #pragma unroll
    for (int u = 0; u < 2; ++u) {
        const int co0 = u * 8 + 2 * c;
        const float b0v = bias[co0];
        const float b1v = bias[co0 + 1];
        #pragma unroll
        for (int j = 0; j < 3; ++j) {
            const int t = 8 * j + g;
            ob[(size_t)co0 * ST_C + (size_t)dE * ST_D + t]       = acc[j][u][0] + b0v;
            ob[(size_t)(co0 + 1) * ST_C + (size_t)dE * ST_D + t] = acc[j][u][1] + b1v;
            ob[(size_t)co0 * ST_C + (size_t)dO * ST_D + t]       = acc[j][u][2] + b0v;
            ob[(size_t)(co0 + 1) * ST_C + (size_t)dO * ST_D + t] = acc[j][u][3] + b1v;
        }
    }
}

extern "C" void kernel_launch(void* const* d_in, const int* in_sizes, int n_in,
                              void* d_out, int out_size) {
    const float* x   = (const float*)d_in[0];
    const float* w   = (const float*)d_in[1];
    const float* bia = (const float*)d_in[2];
    float* out       = (float*)d_out;

    prep_kernel<<<2593, 256>>>(x, w);

    cudaFuncSetAttribute(conv4d_hmma16t_kernel,
                         cudaFuncAttributeMaxDynamicSharedMemorySize, SMEM_BYTES);
    conv4d_hmma16t_kernel<<<1728, 256, SMEM_BYTES>>>(bia, out);
}

// round 14
// speedup vs baseline: 1.1109x; 1.1109x over previous
#include <cuda_runtime.h>
#include <cuda_fp16.h>
#include <cstdint>

// fullConv4d via fp16 mma.sync m16n8k16 (fp32 accum). M=spatial, N=co, K=ci16.
// R14 = R12 structure + h-pair plane reuse: CTA = (b, h-PAIR, w-tile 2, d-tile 8),
// each staged x plane feeds up to 2 output-h consumers (different kh taps, same A
// fragments) -> plane visits 6 -> 4 per CTA (A-LDSM & staging x0.67/output).
// All 81 weight taps staged once per CTA; slab double-buffered via cp.async.

#define ST_T 1
#define ST_D 24
#define ST_W 576
#define ST_H 13824
#define ST_C 331776

#define SLABB   33280                       // 1040 pts * 32B
#define WSB     41472                       // 81 taps * 512B
#define SMEM_BYTES (2 * SLABB + WSB)        // 108032

__device__ uint4 g_xh[1327104];             // 663552 points * 32B (fp16, ci16)
__device__ uint4 g_wf[2592];                // 81 taps * 32 lanes * 16B

static __device__ __forceinline__ uint32_t smem_u32(const void* p) {
    uint32_t a;
    asm("{ .reg .u64 t; cvta.to.shared.u64 t, %1; cvt.u32.u64 %0, t; }" : "=r"(a) : "l"(p));
    return a;
}

static __device__ __forceinline__ uint32_t pack2(float a, float b) {
    __half2 h = __floats2half2_rn(a, b);
    return *reinterpret_cast<uint32_t*>(&h);
}

static __device__ __forceinline__ void cpa16(uint32_t dst, const void* src, uint32_t srcsz) {
    asm volatile("cp.async.cg.shared.global [%0], [%1], 16, %2;"
                 :: "r"(dst), "l"(src), "r"(srcsz));
}

static __device__ __forceinline__ void mma16816(float* d, uint32_t a0, uint32_t a1,
                                                uint32_t a2, uint32_t a3,
                                                uint32_t b0, uint32_t b1) {
    asm volatile(
        "mma.sync.aligned.m16n8k16.row.col.f32.f16.f16.f32 "
        "{%0,%1,%2,%3}, {%4,%5,%6,%7}, {%8,%9}, {%0,%1,%2,%3};"
        : "+f"(d[0]), "+f"(d[1]), "+f"(d[2]), "+f"(d[3])
        : "r"(a0), "r"(a1), "r"(a2), "r"(a3), "r"(b0), "r"(b1));
}

// ---- prep: blocks 0..2591 convert x; block 2592 packs weights ----
__global__ __launch_bounds__(256)
void prep_kernel(const float* __restrict__ x, const float* __restrict__ wgt) {
    if (blockIdx.x == 2592) {
        for (int i = threadIdx.x; i < 2592; i += 256) {
            const int tl = i >> 5, l5 = i & 31;
            const int gg = l5 >> 2, cc = (l5 & 3) << 1;
            const float* wp = wgt + tl;
            #define WG(co, ci) wp[((co) * 16 + (ci)) * 81]
            const uint32_t r0 = pack2(WG(gg, cc),         WG(gg, cc + 1));
            const uint32_t r1 = pack2(WG(gg, cc + 8),     WG(gg, cc + 9));
            const uint32_t r2 = pack2(WG(gg + 8, cc),     WG(gg + 8, cc + 1));
            const uint32_t r3 = pack2(WG(gg + 8, cc + 8), WG(gg + 8, cc + 9));
            #undef WG
            g_wf[i] = make_uint4(r0, r1, r2, r3);
        }
        return;
    }
    const int idx = blockIdx.x * 256 + threadIdx.x;          // 663552 points
    int r = idx;
    const int t = r % 24; r /= 24;
    const int d = r % 24; r /= 24;
    const int w = r % 24; r /= 24;
    const int h = r % 24;
    const int b = r / 24;
    const float* p = x + (size_t)b * 16 * ST_C + h * ST_H + w * ST_W + d * ST_D + t;
    uint32_t v[8];
    #pragma unroll
    for (int j = 0; j < 8; ++j)
        v[j] = pack2(p[(2 * j) * ST_C], p[(2 * j + 1) * ST_C]);
    g_xh[idx * 2]     = make_uint4(v[0], v[1], v[2], v[3]);
    g_xh[idx * 2 + 1] = make_uint4(v[4], v[5], v[6], v[7]);
}

// ---- main ----
__global__ __launch_bounds__(256, 2)
void conv4d_hmma16u_kernel(const float* __restrict__ bias,
                           float* __restrict__ out) {
    extern __shared__ char smc[];
    const uint32_t slabAddr = smem_u32(smc);                 // buf0 | buf1 | ws
    const uint32_t wsAddr   = slabAddr + 2 * SLABB;

    const int tid = threadIdx.x;
    const int wid = tid >> 5;
    const int l   = tid & 31;
    const int g   = l >> 2;
    const int c   = l & 3;
    const int wo  = wid >> 2;
    const int dp  = wid & 3;

    int bi = blockIdx.x;
    const int dt = bi % 3;  bi /= 3;
    const int wt = bi % 12; bi /= 12;
    const int hp = bi % 12; bi /= 12;
    const int b  = bi;
    const int d0 = dt * 8;
    const int w0 = wt * 2;
    const int h0 = hp * 2;

    // x4 per-lane offset (R12): lanes 0-7 L klo, 8-15 H(+26) klo, 16-23 L khi, 24-31 H khi
    const int rowmap = (l & 8) ? (26 + (l & 7)) : (l & 7);
    const uint32_t aOff  = (uint32_t)((wo * 260 + dp * 52 + rowmap) * 32 + (l >> 4) * 16);
    const uint32_t aOff2 = (uint32_t)((wo * 260 + dp * 52 + (l & 7)) * 32 + ((l >> 3) & 1) * 16);

    // ---- precompute staging slots ----
    uint32_t dstOff[9];
    int      srcRest[9];
    uint32_t inR = 0, gV = 0;
    #pragma unroll
    for (int k = 0; k < 9; ++k) {
        const int i = tid + k * 256;
        dstOff[k] = 0; srcRest[k] = 0;
        if (i < 2080) {
            const int o  = i & 1;
            const int pt = i >> 1;
            const int tI = pt % 26;
            const int rr = pt / 26;
            const int dI = rr % 10;
            const int wI = rr / 10;
            inR |= (1u << k);
            dstOff[k] = (uint32_t)(pt * 32 + o * 16);
            const int gw = w0 + wI - 1, gd = d0 + dI - 1, gt = tI - 1;
            if ((unsigned)gw < 24u && (unsigned)gd < 24u && (unsigned)gt < 24u) {
                srcRest[k] = (gw * 576 + gd * 24 + gt) * 32 + o * 16;
                gV |= (1u << k);
            }
        }
    }

    // valid planes gh in [h0-1, h0+2]
    int pl[4], np = 0;
    #pragma unroll
    for (int q = 0; q < 4; ++q) {
        const int gh = h0 - 1 + q;
        if ((unsigned)gh < 24u) pl[np++] = gh;
    }

    const char* xhBase = (const char*)g_xh;

    auto stage_slab = [&](int gh, uint32_t bufAddr) {
        const char* sp = xhBase + (long long)((b * 24 + gh) * 13824) * 32;
        #pragma unroll
        for (int k = 0; k < 9; ++k) {
            if (inR & (1u << k))
                cpa16(bufAddr + dstOff[k], sp + srcRest[k],
                      (gV & (1u << k)) ? 16u : 0u);
        }
    };

    // group 0: all 81 weight taps + slab pl[0]
    {
        const char* wf = (const char*)g_wf;
        #pragma unroll
        for (int k = 0; k < 11; ++k) {
            const int i = tid + k * 256;
            if (i < 2592) cpa16(wsAddr + (uint32_t)(i * 16), wf + i * 16, 16u);
        }
        stage_slab(pl[0], slabAddr);
        asm volatile("cp.async.commit_group;" ::: "memory");
    }
    if (np > 1) {
        stage_slab(pl[1], slabAddr + SLABB);
        asm volatile("cp.async.commit_group;" ::: "memory");
    }
    int issued = (np > 1) ? 2 : 1;

    float acc[2][3][2][4];
    #pragma unroll
    for (int h2 = 0; h2 < 2; ++h2)
        #pragma unroll
        for (int j = 0; j < 3; ++j)
            #pragma unroll
            for (int u = 0; u < 2; ++u)
                #pragma unroll
                for (int q = 0; q < 4; ++q) acc[h2][j][u][q] = 0.0f;

    for (int i = 0; i < np; ++i) {
        if (issued - i == 2) { asm volatile("cp.async.wait_group 1;" ::: "memory"); }
        else                 { asm volatile("cp.async.wait_group 0;" ::: "memory"); }
        __syncthreads();

        const int gh  = pl[i];
        const int kh0 = gh - h0 + 1;            // consumer h0
        const int kh1 = gh - h0;                // consumer h0+1
        const bool m0 = ((unsigned)kh0 < 3u);
        const bool m1 = ((unsigned)kh1 < 3u);

        const uint32_t bufAddr = slabAddr + (uint32_t)((i & 1) * SLABB);
        const uint32_t aLane   = bufAddr + aOff;
        const uint32_t aLane2  = bufAddr + aOff2;
        const uint32_t wL0 = wsAddr + (uint32_t)(kh0 * 13824 + l * 16);
        const uint32_t wL1 = wsAddr + (uint32_t)(kh1 * 13824 + l * 16);

        #pragma unroll
        for (int kw = 0; kw < 3; ++kw) {
            #pragma unroll
            for (int kt = 0; kt < 3; ++kt) {
                const int kwb = kw * 260;
                uint32_t hk0[3], hk1[3];
                // kd = 0: x4 per j, mma into both consumers
                {
                    uint32_t p00 = 0, p01 = 0, p02 = 0, p03 = 0;
                    uint32_t p10 = 0, p11 = 0, p12 = 0, p13 = 0;
                    if (m0)
                        asm volatile("ld.shared.v4.b32 {%0,%1,%2,%3}, [%4];"
                                     : "=r"(p00), "=r"(p01), "=r"(p02), "=r"(p03)
                                     : "r"(wL0 + (uint32_t)((kw * 9 + kt) * 512)));
                    if (m1)
                        asm volatile("ld.shared.v4.b32 {%0,%1,%2,%3}, [%4];"
                                     : "=r"(p10), "=r"(p11), "=r"(p12), "=r"(p13)
                                     : "r"(wL1 + (uint32_t)((kw * 9 + kt) * 512)));
                    #pragma unroll
                    for (int j = 0; j < 3; ++j) {
                        const uint32_t P = (uint32_t)((kwb + kt + 8 * j) * 32);
                        uint32_t a0, a1, a2, a3;
                        asm volatile("ldmatrix.sync.aligned.m8n8.x4.shared.b16 "
                                     "{%0,%1,%2,%3}, [%4];"
                                     : "=r"(a0), "=r"(a1), "=r"(a2), "=r"(a3)
                                     : "r"(aLane + P));
                        if (m0) {
                            mma16816(acc[0][j][0], a0, a1, a2, a3, p00, p01);
                            mma16816(acc[0][j][1], a0, a1, a2, a3, p02, p03);
                        }
                        if (m1) {
                            mma16816(acc[1][j][0], a0, a1, a2, a3, p10, p11);
                            mma16816(acc[1][j][1], a0, a1, a2, a3, p12, p13);
                        }
                        hk0[j] = a1; hk1[j] = a3;
                    }
                }
                // kd = 1, 2: x2 chain, mma into both consumers
                #pragma unroll
                for (int kd = 1; kd < 3; ++kd) {
                    uint32_t p00 = 0, p01 = 0, p02 = 0, p03 = 0;
                    uint32_t p10 = 0, p11 = 0, p12 = 0, p13 = 0;
                    if (m0)
                        asm volatile("ld.shared.v4.b32 {%0,%1,%2,%3}, [%4];"
                                     : "=r"(p00), "=r"(p01), "=r"(p02), "=r"(p03)
                                     : "r"(wL0 + (uint32_t)((kw * 9 + kd * 3 + kt) * 512)));
                    if (m1)
                        asm volatile("ld.shared.v4.b32 {%0,%1,%2,%3}, [%4];"
                                     : "=r"(p10), "=r"(p11), "=r"(p12), "=r"(p13)
                                     : "r"(wL1 + (uint32_t)((kw * 9 + kd * 3 + kt) * 512)));
                    #pragma unroll
                    for (int j = 0; j < 3; ++j) {
                        const uint32_t P2 = (uint32_t)((kwb + (kd + 1) * 26 + kt + 8 * j) * 32);
                        uint32_t n0, n1;
                        asm volatile("ldmatrix.sync.aligned.m8n8.x2.shared.b16 "
                                     "{%0,%1}, [%2];"
                                     : "=r"(n0), "=r"(n1)
                                     : "r"(aLane2 + P2));
                        if (m0) {
                            mma16816(acc[0][j][0], hk0[j], n0, hk1[j], n1, p00, p01);
                            mma16816(acc[0][j][1], hk0[j], n0, hk1[j], n1, p02, p03);
                        }
                        if (m1) {
                            mma16816(acc[1][j][0], hk0[j], n0, hk1[j], n1, p10, p11);
                            mma16816(acc[1][j][1], hk0[j], n0, hk1[j], n1, p12, p13);
                        }
                        hk0[j] = n0; hk1[j] = n1;
                    }
                }
            }
        }

        if (issued < np) {                    // refill buf(issued&1)
            __syncthreads();
            stage_slab(pl[issued], slabAddr + (uint32_t)((issued & 1) * SLABB));
            asm volatile("cp.async.commit_group;" ::: "memory");
            ++issued;
        }
    }

    // ---- epilogue: two h rows ----
    const int dE = d0 + 2 * dp, dO = dE + 1;
    #pragma unroll
    for (int h2 = 0; h2 < 2; ++h2) {
        float* ob = out + (size_t)b * 16 * ST_C + (size_t)(h0 + h2) * ST_H
                    + (size_t)(w0 + wo) * ST_W;
        #pragma unroll
        for (int u = 0; u < 2; ++u) {
            const int co0 = u * 8 + 2 * c;
            const float b0v = bias[co0];
            const float b1v = bias[co0 + 1];
            #pragma unroll
            for (int j = 0; j < 3; ++j) {
                const int t = 8 * j + g;
                ob[(size_t)co0 * ST_C + (size_t)dE * ST_D + t]       = acc[h2][j][u][0] + b0v;
                ob[(size_t)(co0 + 1) * ST_C + (size_t)dE * ST_D + t] = acc[h2][j][u][1] + b1v;
                ob[(size_t)co0 * ST_C + (size_t)dO * ST_D + t]       = acc[h2][j][u][2] + b0v;
                ob[(size_t)(co0 + 1) * ST_C + (size_t)dO * ST_D + t] = acc[h2][j][u][3] + b1v;
            }
        }
    }
}

extern "C" void kernel_launch(void* const* d_in, const int* in_sizes, int n_in,
                              void* d_out, int out_size) {
    const float* x   = (const float*)d_in[0];
    const float* w   = (const float*)d_in[1];
    const float* bia = (const float*)d_in[2];
    float* out       = (float*)d_out;

    prep_kernel<<<2593, 256>>>(x, w);

    cudaFuncSetAttribute(conv4d_hmma16u_kernel,
                         cudaFuncAttributeMaxDynamicSharedMemorySize, SMEM_BYTES);
    conv4d_hmma16u_kernel<<<864, 256, SMEM_BYTES>>>(bia, out);
}